// round 3
// baseline (speedup 1.0000x reference)
#include <cuda_runtime.h>
#include <cuda_bf16.h>
#include <math.h>

// ---------------- model constants ----------------
#define SEQ    257
#define FZR    6
#define FXA    5
#define L_ZR   (FZR*SEQ)      // 1542
#define L_XA   (FXA*SEQ)      // 1285
#define LTOT   (L_ZR + L_XA)  // 2827
#define LTOTP  2832           // padded S row stride (cross)
#define LXAP   1288           // padded S row stride (self)
#define DM     512
#define NHEAD  8
#define HID    2048
#define NBLK   6
#define CDIV(a,b) (((a)+(b)-1)/(b))

// ---------------- scratch (static device memory; no allocs) ----------------
__device__ float g_ACT [LTOT * DM];
__device__ float g_NRM [LTOT * DM];
__device__ float g_QKV [LTOT * 3 * DM];
__device__ float g_ATT [LTOT * DM];
__device__ float g_O   [LTOT * DM];
__device__ float g_B1  [LTOT * DM];
__device__ float g_FF1 [LTOT * 2 * HID];
__device__ float g_H   [LTOT * HID];
__device__ float g_S   [(size_t)NHEAD * L_ZR * LTOTP];
__device__ float g_COND[7 * DM];
__device__ float g_SIL [7 * DM];
__device__ float g_MOD1[7 * 2 * DM];
__device__ float g_MOD2[7 * 2 * DM];
__device__ float g_G1  [7 * DM];
__device__ float g_G2  [7 * DM];

// ---------------- helpers ----------------
__device__ __forceinline__ int cond_of_row(int r) { return (r < L_ZR) ? (r / SEQ) : 6; }

__device__ __forceinline__ unsigned short f2bf(float x) {
    __nv_bfloat16 h = __float2bfloat16(x);
    return __bfloat16_as_ushort(h);
}
__device__ __forceinline__ float bf2f(unsigned short s) {
    return __bfloat162float(__ushort_as_bfloat16(s));
}

__device__ __forceinline__ float blockReduceSum(float v) {
    __shared__ float sh[33];
    int lane = threadIdx.x & 31, w = threadIdx.x >> 5;
    #pragma unroll
    for (int o = 16; o; o >>= 1) v += __shfl_xor_sync(0xffffffffu, v, o);
    if (lane == 0) sh[w] = v;
    __syncthreads();
    if (w == 0) {
        float x = (threadIdx.x < (blockDim.x >> 5)) ? sh[threadIdx.x] : 0.f;
        #pragma unroll
        for (int o = 16; o; o >>= 1) x += __shfl_xor_sync(0xffffffffu, x, o);
        if (lane == 0) sh[32] = x;
    }
    __syncthreads();
    float r = sh[32];
    __syncthreads();
    return r;
}

__device__ __forceinline__ float blockReduceMax(float v) {
    __shared__ float sh[33];
    int lane = threadIdx.x & 31, w = threadIdx.x >> 5;
    #pragma unroll
    for (int o = 16; o; o >>= 1) v = fmaxf(v, __shfl_xor_sync(0xffffffffu, v, o));
    if (lane == 0) sh[w] = v;
    __syncthreads();
    if (w == 0) {
        float x = (threadIdx.x < (blockDim.x >> 5)) ? sh[threadIdx.x] : -1e30f;
        #pragma unroll
        for (int o = 16; o; o >>= 1) x = fmaxf(x, __shfl_xor_sync(0xffffffffu, x, o));
        if (lane == 0) sh[32] = x;
    }
    __syncthreads();
    float r = sh[32];
    __syncthreads();
    return r;
}

#define MMA_BF16(d, a, b0v, b1v)                                             \
    asm volatile("mma.sync.aligned.m16n8k16.row.col.f32.bf16.bf16.f32 "      \
                 "{%0,%1,%2,%3}, {%4,%5,%6,%7}, {%8,%9}, {%0,%1,%2,%3};"     \
                 : "+f"(d[0]), "+f"(d[1]), "+f"(d[2]), "+f"(d[3])            \
                 : "r"(a[0]), "r"(a[1]), "r"(a[2]), "r"(a[3]),               \
                   "r"(b0v), "r"(b1v))

// ============================================================================
// Tensor-core GEMM: C[M,N] = A[M,K] @ B[K,N] (+bias/gate/scale per ep)
// A row-major fp32. btmode=0: B row-major [K][N]; btmode=1: Bt row-major [N][K].
// Per-z offsets (elements): Asz/Bsz/Csz.  ep: 0=+bias, 1=(+bias)*gate[cond], 2=*scale, 3=raw
// bf16 hi/lo split, 3-term mma: full ~16-bit mantissa accuracy.
// ============================================================================
__global__ __launch_bounds__(256) void tcgemm(
    const float* __restrict__ A, int lda, long Asz,
    const float* __restrict__ B, int ldb, long Bsz, int btmode,
    const float* __restrict__ bias,
    float* __restrict__ C, int ldc, long Csz,
    int M, int N, int K,
    int ep, const float* __restrict__ gate, float scale)
{
    __shared__ __align__(16) unsigned short Ah[128 * 40], Al[128 * 40];
    __shared__ __align__(16) unsigned short Bh[128 * 40], Bl[128 * 40];

    const int tid = threadIdx.x, lane = tid & 31, warp = tid >> 5;
    const int wm = warp & 3, wn = warp >> 2;      // 4 x 2 warp grid
    const int g = lane >> 2, tq = lane & 3;
    const int m0 = blockIdx.y * 128, n0 = blockIdx.x * 128;

    A += (long)blockIdx.z * Asz;
    B += (long)blockIdx.z * Bsz;
    C += (long)blockIdx.z * Csz;

    float acc[2][8][4];
    #pragma unroll
    for (int i = 0; i < 2; i++)
        #pragma unroll
        for (int j = 0; j < 8; j++)
            #pragma unroll
            for (int l = 0; l < 4; l++) acc[i][j][l] = 0.f;

    const int arow = tid >> 1;         // 0..127 (A / Bt fill row)
    const int akb  = (tid & 1) * 16;   // k half
    const int bnl  = tid & 127;        // btmode0: n within tile
    const int bkb  = (tid >> 7) * 16;  // btmode0: k half

    for (int k0 = 0; k0 < K; k0 += 32) {
        // ---- fill A tile (hi/lo bf16) ----
        {
            const int gm = m0 + arow;
            #pragma unroll
            for (int q = 0; q < 4; q++) {
                const int kq = akb + q * 4;
                float x0, x1, x2, x3;
                if (gm < M && (k0 + kq + 3) < K) {
                    float4 v = *(const float4*)(A + (size_t)gm * lda + k0 + kq);
                    x0 = v.x; x1 = v.y; x2 = v.z; x3 = v.w;
                } else {
                    x0 = (gm < M && k0 + kq + 0 < K) ? A[(size_t)gm * lda + k0 + kq + 0] : 0.f;
                    x1 = (gm < M && k0 + kq + 1 < K) ? A[(size_t)gm * lda + k0 + kq + 1] : 0.f;
                    x2 = (gm < M && k0 + kq + 2 < K) ? A[(size_t)gm * lda + k0 + kq + 2] : 0.f;
                    x3 = (gm < M && k0 + kq + 3 < K) ? A[(size_t)gm * lda + k0 + kq + 3] : 0.f;
                }
                unsigned short h0 = f2bf(x0), h1 = f2bf(x1), h2 = f2bf(x2), h3 = f2bf(x3);
                unsigned short l0 = f2bf(x0 - bf2f(h0)), l1 = f2bf(x1 - bf2f(h1));
                unsigned short l2 = f2bf(x2 - bf2f(h2)), l3 = f2bf(x3 - bf2f(h3));
                *(unsigned*)&Ah[arow * 40 + kq]     = (unsigned)h0 | ((unsigned)h1 << 16);
                *(unsigned*)&Ah[arow * 40 + kq + 2] = (unsigned)h2 | ((unsigned)h3 << 16);
                *(unsigned*)&Al[arow * 40 + kq]     = (unsigned)l0 | ((unsigned)l1 << 16);
                *(unsigned*)&Al[arow * 40 + kq + 2] = (unsigned)l2 | ((unsigned)l3 << 16);
            }
        }
        // ---- fill B tile ----
        if (btmode) {   // Bt row-major [N][K] — same pattern as A
            const int gn = n0 + arow;
            #pragma unroll
            for (int q = 0; q < 4; q++) {
                const int kq = akb + q * 4;
                float x0, x1, x2, x3;
                if (gn < N && (k0 + kq + 3) < K) {
                    float4 v = *(const float4*)(B + (size_t)gn * ldb + k0 + kq);
                    x0 = v.x; x1 = v.y; x2 = v.z; x3 = v.w;
                } else {
                    x0 = (gn < N && k0 + kq + 0 < K) ? B[(size_t)gn * ldb + k0 + kq + 0] : 0.f;
                    x1 = (gn < N && k0 + kq + 1 < K) ? B[(size_t)gn * ldb + k0 + kq + 1] : 0.f;
                    x2 = (gn < N && k0 + kq + 2 < K) ? B[(size_t)gn * ldb + k0 + kq + 2] : 0.f;
                    x3 = (gn < N && k0 + kq + 3 < K) ? B[(size_t)gn * ldb + k0 + kq + 3] : 0.f;
                }
                unsigned short h0 = f2bf(x0), h1 = f2bf(x1), h2 = f2bf(x2), h3 = f2bf(x3);
                unsigned short l0 = f2bf(x0 - bf2f(h0)), l1 = f2bf(x1 - bf2f(h1));
                unsigned short l2 = f2bf(x2 - bf2f(h2)), l3 = f2bf(x3 - bf2f(h3));
                *(unsigned*)&Bh[arow * 40 + kq]     = (unsigned)h0 | ((unsigned)h1 << 16);
                *(unsigned*)&Bh[arow * 40 + kq + 2] = (unsigned)h2 | ((unsigned)h3 << 16);
                *(unsigned*)&Bl[arow * 40 + kq]     = (unsigned)l0 | ((unsigned)l1 << 16);
                *(unsigned*)&Bl[arow * 40 + kq + 2] = (unsigned)l2 | ((unsigned)l3 << 16);
            }
        } else {        // B row-major [K][N] — transpose into [n][k] smem
            unsigned short hh[16], ll[16];
            const int gn = n0 + bnl;
            #pragma unroll
            for (int i = 0; i < 16; i++) {
                int kk = k0 + bkb + i;
                float x = (kk < K && gn < N) ? B[(size_t)kk * ldb + gn] : 0.f;
                hh[i] = f2bf(x);
                ll[i] = f2bf(x - bf2f(hh[i]));
            }
            #pragma unroll
            for (int p = 0; p < 8; p++) {
                *(unsigned*)&Bh[bnl * 40 + bkb + 2 * p] = (unsigned)hh[2*p] | ((unsigned)hh[2*p+1] << 16);
                *(unsigned*)&Bl[bnl * 40 + bkb + 2 * p] = (unsigned)ll[2*p] | ((unsigned)ll[2*p+1] << 16);
            }
        }
        __syncthreads();

        #pragma unroll
        for (int kk = 0; kk < 32; kk += 16) {
            unsigned ah[2][4], al[2][4];
            #pragma unroll
            for (int mt = 0; mt < 2; mt++) {
                const int r = wm * 32 + mt * 16 + g;
                ah[mt][0] = *(unsigned*)&Ah[r * 40 + kk + 2 * tq];
                ah[mt][1] = *(unsigned*)&Ah[(r + 8) * 40 + kk + 2 * tq];
                ah[mt][2] = *(unsigned*)&Ah[r * 40 + kk + 8 + 2 * tq];
                ah[mt][3] = *(unsigned*)&Ah[(r + 8) * 40 + kk + 8 + 2 * tq];
                al[mt][0] = *(unsigned*)&Al[r * 40 + kk + 2 * tq];
                al[mt][1] = *(unsigned*)&Al[(r + 8) * 40 + kk + 2 * tq];
                al[mt][2] = *(unsigned*)&Al[r * 40 + kk + 8 + 2 * tq];
                al[mt][3] = *(unsigned*)&Al[(r + 8) * 40 + kk + 8 + 2 * tq];
            }
            #pragma unroll
            for (int nt = 0; nt < 8; nt++) {
                const int c = wn * 64 + nt * 8 + g;
                unsigned bh0 = *(unsigned*)&Bh[c * 40 + kk + 2 * tq];
                unsigned bh1 = *(unsigned*)&Bh[c * 40 + kk + 8 + 2 * tq];
                unsigned bl0 = *(unsigned*)&Bl[c * 40 + kk + 2 * tq];
                unsigned bl1 = *(unsigned*)&Bl[c * 40 + kk + 8 + 2 * tq];
                #pragma unroll
                for (int mt = 0; mt < 2; mt++) {
                    MMA_BF16(acc[mt][nt], ah[mt], bh0, bh1);
                    MMA_BF16(acc[mt][nt], ah[mt], bl0, bl1);
                    MMA_BF16(acc[mt][nt], al[mt], bh0, bh1);
                }
            }
        }
        __syncthreads();
    }

    // ---- epilogue ----
    #pragma unroll
    for (int mt = 0; mt < 2; mt++) {
        const int r = m0 + wm * 32 + mt * 16 + g;
        #pragma unroll
        for (int nt = 0; nt < 8; nt++) {
            const int c = n0 + wn * 64 + nt * 8 + 2 * tq;
            #pragma unroll
            for (int half = 0; half < 2; half++) {
                const int rr = r + half * 8;
                if (rr >= M) continue;
                const int cidx = (ep == 1) ? cond_of_row(rr) : 0;
                #pragma unroll
                for (int jj = 0; jj < 2; jj++) {
                    const int cc = c + jj;
                    if (cc >= N) continue;
                    float v = acc[mt][nt][half * 2 + jj];
                    if (ep == 0)      v += bias[cc];
                    else if (ep == 1) v = (v + bias[cc]) * gate[cidx * 512 + cc];
                    else if (ep == 2) v *= scale;
                    C[(size_t)rr * ldc + cc] = v;
                }
            }
        }
    }
}

// ---------------- small cond GEMM: C[7,N] = A[7,512] @ W[512,N] + bias ----------------
__global__ __launch_bounds__(256) void condgemm(
    const float* __restrict__ Acond, const float* __restrict__ W, int N,
    const float* __restrict__ bias, float* __restrict__ Cout)
{
    __shared__ float sA[7 * 512];
    for (int i = threadIdx.x; i < 7 * 512; i += 256) sA[i] = Acond[i];
    __syncthreads();
    const int n = blockIdx.x * 256 + threadIdx.x;
    if (n >= N) return;
    float acc[7] = {};
    #pragma unroll 4
    for (int k = 0; k < 512; k++) {
        float w = W[(size_t)k * N + n];
        #pragma unroll
        for (int m = 0; m < 7; m++) acc[m] += sA[m * 512 + k] * w;
    }
    float b = bias[n];
    #pragma unroll
    for (int m = 0; m < 7; m++) Cout[m * N + n] = acc[m] + b;
}

// ---------------- masked softmax over S rows ----------------
__global__ __launch_bounds__(256) void softmax_kernel(
    float* __restrict__ S, long Sstride, int Nk, int ldS, int isCross)
{
    const int r = blockIdx.x, h = blockIdx.y;
    float* row = S + (size_t)h * Sstride + (size_t)r * ldS;
    const int fq = r / SEQ;
    int a0, a1, b0, b1;
    if (isCross) {
        a0 = fq * SEQ; a1 = a0 + SEQ;
        int j0 = (fq >= 4) ? (fq - 4) : 0;
        b0 = L_ZR + j0 * SEQ; b1 = L_ZR + fq * SEQ;
    } else {
        a0 = 0; a1 = (fq + 1) * SEQ; b0 = 0; b1 = 0;
    }
    float m = -1e30f;
    for (int j = a0 + threadIdx.x; j < a1; j += 256) m = fmaxf(m, row[j]);
    for (int j = b0 + threadIdx.x; j < b1; j += 256) m = fmaxf(m, row[j]);
    m = blockReduceMax(m);
    float s = 0.f;
    for (int j = threadIdx.x; j < Nk; j += 256) {
        bool in = (j >= a0 && j < a1) || (j >= b0 && j < b1);
        float e = in ? expf(row[j] - m) : 0.f;
        row[j] = e; s += e;
    }
    s = blockReduceSum(s);
    float inv = 1.f / s;
    for (int j = threadIdx.x; j < Nk; j += 256) row[j] *= inv;
}

// ---------------- patch/register/action embedding -> g_ACT ----------------
__global__ __launch_bounds__(256) void embed_kernel(
    const float* __restrict__ z, const float* __restrict__ frames,
    const int* __restrict__ actions,
    const float* __restrict__ Wp, const float* __restrict__ bp,
    const float* __restrict__ regs, const float* __restrict__ pe,
    const float* __restrict__ aemb)
{
    const int r = blockIdx.x;
    const bool isZ = (r < L_ZR);
    const int f = isZ ? (r / SEQ) : ((r - L_ZR) / SEQ);
    const int t = isZ ? (r % SEQ) : ((r - L_ZR) % SEQ);
    __shared__ float pv[12];
    if (t < 256 && threadIdx.x < 12) {
        int c = threadIdx.x >> 2, py = (threadIdx.x >> 1) & 1, px = threadIdx.x & 1;
        int ph = t >> 4, pw = t & 15;
        const float* src = isZ ? (z + f * 3072) : (frames + f * 3072);
        pv[threadIdx.x] = src[c * 1024 + (ph * 2 + py) * 32 + (pw * 2 + px)];
    }
    __syncthreads();
    for (int d = threadIdx.x; d < DM; d += 256) {
        float val;
        if (t == 256) {
            val = isZ ? regs[d] : aemb[actions[f] * DM + d];
        } else {
            float s = bp[d] + pe[t * DM + d];
            #pragma unroll
            for (int k = 0; k < 12; k++) s += pv[k] * Wp[k * DM + d];
            val = s;
        }
        g_ACT[(size_t)r * DM + d] = val;
    }
}

// ---------------- cond vectors (7 = 6 noisy + 1 clean), + silu ----------------
__global__ __launch_bounds__(256) void cond_kernel(
    const float* __restrict__ temb, const int* __restrict__ ts)
{
    const int c = blockIdx.x;
    const int row = (c < 6) ? ts[c] : 0;
    for (int d = threadIdx.x; d < DM; d += 256) {
        float v = temb[(size_t)row * DM + d];
        g_COND[c * DM + d] = v;
        g_SIL[c * DM + d] = v / (1.f + expf(-v));
    }
}

// ---------------- LN + AdaLN modulation ----------------
__global__ __launch_bounds__(256) void lnmod_kernel(
    const float* __restrict__ X, const float* __restrict__ MOD, float* __restrict__ Y)
{
    const int r = blockIdx.x;
    const int cidx = cond_of_row(r);
    const size_t base = (size_t)r * DM;
    const int d0 = threadIdx.x, d1 = threadIdx.x + 256;
    float v0 = X[base + d0], v1 = X[base + d1];
    float mu = blockReduceSum(v0 + v1) * (1.f / 512.f);
    float c0 = v0 - mu, c1 = v1 - mu;
    float var = blockReduceSum(c0 * c0 + c1 * c1) * (1.f / 512.f);
    float inv = rsqrtf(var + 1e-5f);
    const float* sc = MOD + cidx * 1024;
    Y[base + d0] = c0 * inv * (1.f + sc[d0]) + sc[512 + d0];
    Y[base + d1] = c1 * inv * (1.f + sc[d1]) + sc[512 + d1];
}

// ---------------- gate1 * NRM + attn_out, then LN + mod2 -> B1 ----------------
__global__ __launch_bounds__(256) void gatereslnmod_kernel(
    const float* __restrict__ NRM, const float* __restrict__ O,
    const float* __restrict__ G, const float* __restrict__ MOD, float* __restrict__ Y)
{
    const int r = blockIdx.x;
    const int cidx = cond_of_row(r);
    const size_t base = (size_t)r * DM;
    const int d0 = threadIdx.x, d1 = threadIdx.x + 256;
    float u0 = NRM[base + d0] * G[cidx * 512 + d0] + O[base + d0];
    float u1 = NRM[base + d1] * G[cidx * 512 + d1] + O[base + d1];
    float mu = blockReduceSum(u0 + u1) * (1.f / 512.f);
    float c0 = u0 - mu, c1 = u1 - mu;
    float var = blockReduceSum(c0 * c0 + c1 * c1) * (1.f / 512.f);
    float inv = rsqrtf(var + 1e-5f);
    const float* sc = MOD + cidx * 1024;
    Y[base + d0] = c0 * inv * (1.f + sc[d0]) + sc[512 + d0];
    Y[base + d1] = c1 * inv * (1.f + sc[d1]) + sc[512 + d1];
}

// ---------------- GEGLU elementwise ----------------
__global__ __launch_bounds__(256) void geglu_kernel()
{
    int idx = blockIdx.x * 256 + threadIdx.x;
    if (idx >= LTOT * HID) return;
    int r = idx / HID, c = idx % HID;
    float a = g_FF1[(size_t)r * (2 * HID) + c];
    float g = g_FF1[(size_t)r * (2 * HID) + HID + c];
    g_H[idx] = a * 0.5f * g * (1.f + erff(g * 0.70710678118654752f));
}

// ---------------- unpatch ----------------
__global__ __launch_bounds__(256) void unpatch_kernel(
    const float* __restrict__ Wu, const float* __restrict__ bu, float* __restrict__ out)
{
    int idx = blockIdx.x * 256 + threadIdx.x;
    if (idx >= FZR * 256 * 12) return;
    int j = idx % 12, tl = idx / 12;
    int f = tl >> 8, t = tl & 255;
    const float* a = g_ACT + (size_t)(f * SEQ + t) * DM;
    float s = bu[j];
    #pragma unroll 4
    for (int d = 0; d < DM; d++) s += a[d] * Wu[d * 12 + j];
    int c = j >> 2, py = (j >> 1) & 1, px = j & 1;
    int ph = t >> 4, pw = t & 15;
    out[f * 3072 + c * 1024 + (ph * 2 + py) * 32 + (pw * 2 + px)] = s;
}

// ---------------- host orchestration ----------------
extern "C" void kernel_launch(void* const* d_in, const int* in_sizes, int n_in,
                              void* d_out, int out_size)
{
    const float* z      = (const float*)d_in[0];
    const float* frames = (const float*)d_in[1];
    const int*   actions= (const int*)  d_in[2];
    const int*   ts     = (const int*)  d_in[3];
    const float* Wp     = (const float*)d_in[4];
    const float* bp     = (const float*)d_in[5];
    const float* Wu     = (const float*)d_in[6];
    const float* bu     = (const float*)d_in[7];
    const float* regs   = (const float*)d_in[8];
    const float* pe     = (const float*)d_in[9];
    const float* aemb   = (const float*)d_in[10];
    const float* temb   = (const float*)d_in[11];
    const float* Wm1    = (const float*)d_in[12];
    const float* bm1    = (const float*)d_in[13];
    const float* Wm2    = (const float*)d_in[14];
    const float* bm2    = (const float*)d_in[15];
    const float* Wq     = (const float*)d_in[16];
    const float* bq     = (const float*)d_in[17];
    const float* Wk     = (const float*)d_in[18];
    const float* bk     = (const float*)d_in[19];
    const float* Wv     = (const float*)d_in[20];
    const float* bv     = (const float*)d_in[21];
    const float* Wo     = (const float*)d_in[22];
    const float* bo     = (const float*)d_in[23];
    const float* Wg1    = (const float*)d_in[24];
    const float* bg1    = (const float*)d_in[25];
    const float* Wg2    = (const float*)d_in[26];
    const float* bg2    = (const float*)d_in[27];
    const float* Wge    = (const float*)d_in[28];
    const float* bge    = (const float*)d_in[29];
    const float* Wff    = (const float*)d_in[30];
    const float* bff    = (const float*)d_in[31];

    float *ACT, *NRM, *QKV, *ATT, *O, *B1, *FF1, *H, *S;
    float *COND, *SIL, *MOD1, *MOD2, *G1, *G2;
    cudaGetSymbolAddress((void**)&ACT,  g_ACT);
    cudaGetSymbolAddress((void**)&NRM,  g_NRM);
    cudaGetSymbolAddress((void**)&QKV,  g_QKV);
    cudaGetSymbolAddress((void**)&ATT,  g_ATT);
    cudaGetSymbolAddress((void**)&O,    g_O);
    cudaGetSymbolAddress((void**)&B1,   g_B1);
    cudaGetSymbolAddress((void**)&FF1,  g_FF1);
    cudaGetSymbolAddress((void**)&H,    g_H);
    cudaGetSymbolAddress((void**)&S,    g_S);
    cudaGetSymbolAddress((void**)&COND, g_COND);
    cudaGetSymbolAddress((void**)&SIL,  g_SIL);
    cudaGetSymbolAddress((void**)&MOD1, g_MOD1);
    cudaGetSymbolAddress((void**)&MOD2, g_MOD2);
    cudaGetSymbolAddress((void**)&G1,   g_G1);
    cudaGetSymbolAddress((void**)&G2,   g_G2);

    embed_kernel<<<LTOT, 256>>>(z, frames, actions, Wp, bp, regs, pe, aemb);
    cond_kernel<<<7, 256>>>(temb, ts);

    const long SC = (long)L_ZR * LTOTP;   // cross S per-head stride
    const long SS = (long)L_XA * LXAP;    // self  S per-head stride

    for (int i = 0; i < NBLK; i++) {
        const float* Wm1i = Wm1 + (size_t)i * DM * 2 * DM;
        const float* bm1i = bm1 + (size_t)i * 2 * DM;
        const float* Wm2i = Wm2 + (size_t)i * DM * 2 * DM;
        const float* bm2i = bm2 + (size_t)i * 2 * DM;
        const float* Wqi  = Wq  + (size_t)i * DM * DM;
        const float* bqi  = bq  + (size_t)i * DM;
        const float* Wki  = Wk  + (size_t)i * DM * DM;
        const float* bki  = bk  + (size_t)i * DM;
        const float* Wvi  = Wv  + (size_t)i * DM * DM;
        const float* bvi  = bv  + (size_t)i * DM;
        const float* Woi  = Wo  + (size_t)i * DM * DM;
        const float* boi  = bo  + (size_t)i * DM;
        const float* Wg1i = Wg1 + (size_t)i * DM * DM;
        const float* bg1i = bg1 + (size_t)i * DM;
        const float* Wg2i = Wg2 + (size_t)i * DM * DM;
        const float* bg2i = bg2 + (size_t)i * DM;
        const float* Wgei = Wge + (size_t)i * DM * 2 * HID;
        const float* bgei = bge + (size_t)i * 2 * HID;
        const float* Wffi = Wff + (size_t)i * HID * DM;
        const float* bffi = bff + (size_t)i * DM;

        // AdaLN scale/shift + gates for the 7 cond vectors
        condgemm<<<4, 256>>>(SIL,  Wm1i, 1024, bm1i, MOD1);
        condgemm<<<4, 256>>>(SIL,  Wm2i, 1024, bm2i, MOD2);
        condgemm<<<2, 256>>>(COND, Wg1i, 512,  bg1i, G1);
        condgemm<<<2, 256>>>(COND, Wg2i, 512,  bg2i, G2);

        // LN + mod1 on both streams
        lnmod_kernel<<<LTOT, 256>>>(ACT, MOD1, NRM);

        // QKV projections (shared between cross & self since xkv = [zrn; xan])
        tcgemm<<<dim3(4, 23, 1), 256>>>(NRM, 512, 0, Wqi, 512, 0, 0, bqi, QKV + 0,    1536, 0, LTOT, 512, 512, 0, nullptr, 0.f);
        tcgemm<<<dim3(4, 23, 1), 256>>>(NRM, 512, 0, Wki, 512, 0, 0, bki, QKV + 512,  1536, 0, LTOT, 512, 512, 0, nullptr, 0.f);
        tcgemm<<<dim3(4, 23, 1), 256>>>(NRM, 512, 0, Wvi, 512, 0, 0, bvi, QKV + 1024, 1536, 0, LTOT, 512, 512, 0, nullptr, 0.f);

        // ---- cross attention (q = zr, kv = all) ----
        tcgemm<<<dim3(CDIV(LTOT,128), CDIV(L_ZR,128), NHEAD), 256>>>(
            QKV, 1536, 64, QKV + 512, 1536, 64, 1, nullptr,
            S, LTOTP, SC, L_ZR, LTOT, 64, 2, nullptr, 0.125f);
        softmax_kernel<<<dim3(L_ZR, NHEAD), 256>>>(S, SC, LTOT, LTOTP, 1);
        tcgemm<<<dim3(1, CDIV(L_ZR,128), NHEAD), 256>>>(
            S, LTOTP, SC, QKV + 1024, 1536, 64, 0, nullptr,
            ATT, 512, 64, L_ZR, 64, LTOT, 3, nullptr, 0.f);

        // ---- self attention (q = kv = xa) ----
        tcgemm<<<dim3(CDIV(L_XA,128), CDIV(L_XA,128), NHEAD), 256>>>(
            QKV + (size_t)L_ZR * 1536, 1536, 64, QKV + (size_t)L_ZR * 1536 + 512, 1536, 64, 1, nullptr,
            S, LXAP, SS, L_XA, L_XA, 64, 2, nullptr, 0.125f);
        softmax_kernel<<<dim3(L_XA, NHEAD), 256>>>(S, SS, L_XA, LXAP, 0);
        tcgemm<<<dim3(1, CDIV(L_XA,128), NHEAD), 256>>>(
            S, LXAP, SS, QKV + (size_t)L_ZR * 1536 + 1024, 1536, 64, 0, nullptr,
            ATT + (size_t)L_ZR * 512, 512, 64, L_XA, 64, L_XA, 3, nullptr, 0.f);

        // output projection
        tcgemm<<<dim3(4, 23, 1), 256>>>(ATT, 512, 0, Woi, 512, 0, 0, boi, O, 512, 0, LTOT, 512, 512, 0, nullptr, 0.f);

        // gate1*NRM + attn, LN + mod2
        gatereslnmod_kernel<<<LTOT, 256>>>(NRM, O, G1, MOD2, B1);

        // GEGLU FFN with gate2 fused into ffout epilogue -> new ACT
        tcgemm<<<dim3(32, 23, 1), 256>>>(B1, 512, 0, Wgei, 4096, 0, 0, bgei, FF1, 4096, 0, LTOT, 4096, 512, 0, nullptr, 0.f);
        geglu_kernel<<<CDIV(LTOT * HID, 256), 256>>>();
        tcgemm<<<dim3(4, 23, 1), 256>>>(H, 2048, 0, Wffi, 512, 0, 0, bffi, ACT, 512, 0, LTOT, 512, 2048, 1, G2, 0.f);
    }

    unpatch_kernel<<<CDIV(FZR * 256 * 12, 256), 256>>>(Wu, bu, (float*)d_out);
}

// round 5
// speedup vs baseline: 1.8660x; 1.8660x over previous
#include <cuda_runtime.h>
#include <cuda_bf16.h>
#include <math.h>

// ---------------- model constants ----------------
#define SEQ    257
#define FZR    6
#define FXA    5
#define L_ZR   1542
#define L_XA   1285
#define LTOT   2827
#define KP_C   2848            // padded key dim (cross), mult of 32
#define KP_S   1312            // padded key dim (self),  mult of 32
#define DM     512
#define NHEAD  8
#define HID    2048
#define NBLK   6
#define CDIV(a,b) (((a)+(b)-1)/(b))
typedef unsigned short ush;

// ---------------- scratch (static device memory; no allocs) ----------------
__device__ float g_ACT [LTOT * DM];
__device__ float g_NRM [LTOT * DM];
__device__ float g_O   [LTOT * DM];
__device__ float g_FF1 [LTOT * 2 * HID];
__device__ float g_S   [(size_t)NHEAD * L_ZR * KP_C];

__device__ ush g_NRMh[LTOT * DM],      g_NRMl[LTOT * DM];
__device__ ush g_QKVh[LTOT * 3 * DM],  g_QKVl[LTOT * 3 * DM];
__device__ ush g_VTh [DM * KP_C],      g_VTl [DM * KP_C];     // [h*64+d][key]
__device__ ush g_Ph  [(size_t)NHEAD * L_ZR * KP_C], g_Pl[(size_t)NHEAD * L_ZR * KP_C];
__device__ ush g_PSh [(size_t)NHEAD * L_XA * KP_S], g_PSl[(size_t)NHEAD * L_XA * KP_S];
__device__ ush g_ATTh[LTOT * DM],      g_ATTl[LTOT * DM];
__device__ ush g_B1h [LTOT * DM],      g_B1l [LTOT * DM];
__device__ ush g_Hh  [LTOT * HID],     g_Hl  [LTOT * HID];

__device__ ush g_Wqkvh[NBLK * 3 * DM * DM], g_Wqkvl[NBLK * 3 * DM * DM];  // [1536][512]
__device__ ush g_Woh  [NBLK * DM * DM],     g_Wol  [NBLK * DM * DM];      // [512][512]
__device__ ush g_Wgeh [NBLK * 2 * HID * DM],g_Wgel [NBLK * 2 * HID * DM]; // [4096][512]
__device__ ush g_Wffh [NBLK * DM * HID],    g_Wffl [NBLK * DM * HID];     // [512][2048]
__device__ float g_bQKV[NBLK * 3 * DM];

__device__ float g_COND[7 * DM];
__device__ float g_SIL [7 * DM];
__device__ float g_MOD1[NBLK * 7 * 2 * DM];
__device__ float g_MOD2[NBLK * 7 * 2 * DM];
__device__ float g_G1  [NBLK * 7 * DM];
__device__ float g_G2  [NBLK * 7 * DM];

// ---------------- helpers ----------------
__device__ __forceinline__ int cond_of_row(int r) { return (r < L_ZR) ? (r / SEQ) : 6; }
__device__ __forceinline__ ush f2bf(float x) { return __bfloat16_as_ushort(__float2bfloat16(x)); }
__device__ __forceinline__ float bf2f(ush s) { return __bfloat162float(__ushort_as_bfloat16(s)); }

__device__ __forceinline__ float blockReduceSum(float v) {
    __shared__ float sh[33];
    int lane = threadIdx.x & 31, w = threadIdx.x >> 5;
    #pragma unroll
    for (int o = 16; o; o >>= 1) v += __shfl_xor_sync(0xffffffffu, v, o);
    if (lane == 0) sh[w] = v;
    __syncthreads();
    if (w == 0) {
        float x = (threadIdx.x < (blockDim.x >> 5)) ? sh[threadIdx.x] : 0.f;
        #pragma unroll
        for (int o = 16; o; o >>= 1) x += __shfl_xor_sync(0xffffffffu, x, o);
        if (lane == 0) sh[32] = x;
    }
    __syncthreads();
    float r = sh[32];
    __syncthreads();
    return r;
}

__device__ __forceinline__ float blockReduceMax(float v) {
    __shared__ float sh[33];
    int lane = threadIdx.x & 31, w = threadIdx.x >> 5;
    #pragma unroll
    for (int o = 16; o; o >>= 1) v = fmaxf(v, __shfl_xor_sync(0xffffffffu, v, o));
    if (lane == 0) sh[w] = v;
    __syncthreads();
    if (w == 0) {
        float x = (threadIdx.x < (blockDim.x >> 5)) ? sh[threadIdx.x] : -1e30f;
        #pragma unroll
        for (int o = 16; o; o >>= 1) x = fmaxf(x, __shfl_xor_sync(0xffffffffu, x, o));
        if (lane == 0) sh[32] = x;
    }
    __syncthreads();
    float r = sh[32];
    __syncthreads();
    return r;
}

#define MMA_BF16(d, a, b0v, b1v)                                             \
    asm volatile("mma.sync.aligned.m16n8k16.row.col.f32.bf16.bf16.f32 "      \
                 "{%0,%1,%2,%3}, {%4,%5,%6,%7}, {%8,%9}, {%0,%1,%2,%3};"     \
                 : "+f"(d[0]), "+f"(d[1]), "+f"(d[2]), "+f"(d[3])            \
                 : "r"(a[0]), "r"(a[1]), "r"(a[2]), "r"(a[3]),               \
                   "r"(b0v), "r"(b1v))

// ============================================================================
// bf16-pair tensor-core GEMM. A [M][K], B [N][K] (both bf16 hi/lo, row-major).
// Sources guarantee zeros in [K, align32(K)) padding where applicable.
// mm: 0 none | 1 cross-scores tile skip | 2 cross-PV k-segments
//     3 self-scores tile skip | 4 self-PV k-range
// ep: 0 +bias | 1 (+bias)*gate[cond] | 2 *scale | 3 raw
// Output: Cf (fp32) if non-null, else bf16 pair Ch/Cl.
// ============================================================================
__global__ __launch_bounds__(256) void tcgemm_bf(
    const ush* __restrict__ Ah, const ush* __restrict__ Al, int lda, long Asz,
    const ush* __restrict__ Bh, const ush* __restrict__ Bl, int ldb, long Bsz, int balign,
    const float* __restrict__ bias,
    float* __restrict__ Cf, ush* __restrict__ Ch, ush* __restrict__ Cl, int ldc, long Csz,
    int M, int N, int K, int mm, const float* __restrict__ gate, float scale, int ep)
{
    __shared__ __align__(16) ush sAh[128 * 40], sAl[128 * 40];
    __shared__ __align__(16) ush sBh[128 * 40], sBl[128 * 40];

    const int tid = threadIdx.x, lane = tid & 31, warp = tid >> 5;
    const int wm = warp & 3, wn = warp >> 2;
    const int g = lane >> 2, tq = lane & 3;
    const int m0 = blockIdx.y * 128, n0 = blockIdx.x * 128;

    // ---- k segments / tile skip ----
    int s0a = 0, s1a = (K + 31) & ~31, s0b = 0, s1b = 0;
    if (mm == 1 || mm == 2) {
        int f0 = m0 / SEQ, f1 = min(m0 + 127, M - 1) / SEQ;
        int ra0 = (f0 * SEQ) & ~31, ra1 = ((f1 + 1) * SEQ + 31) & ~31;
        int b0v = L_ZR + ((f0 > 4) ? (f0 - 4) : 0) * SEQ, b1v = L_ZR + f1 * SEQ;
        int rb0 = b0v & ~31, rb1 = (b1v + 31) & ~31;
        if (b1v <= b0v) { rb0 = 0; rb1 = 0; }
        if (rb1 > rb0 && rb0 < ra1) rb0 = ra1;
        if (mm == 2) { s0a = ra0; s1a = ra1; s0b = rb0; s1b = rb1; }
        else {
            bool hit = (n0 < ra1 && n0 + 128 > ra0) ||
                       (rb1 > rb0 && n0 < rb1 && n0 + 128 > rb0);
            if (!hit) return;
        }
    } else if (mm == 3 || mm == 4) {
        int f1 = min(m0 + 127, M - 1) / SEQ;
        int r1 = ((f1 + 1) * SEQ + 31) & ~31;
        if (mm == 4) s1a = r1;
        else if (n0 >= r1) return;
    }

    Ah += (long)blockIdx.z * Asz;  Al += (long)blockIdx.z * Asz;
    Bh += (long)blockIdx.z * Bsz;  Bl += (long)blockIdx.z * Bsz;

    float acc[2][8][4];
    #pragma unroll
    for (int i = 0; i < 2; i++)
        #pragma unroll
        for (int j = 0; j < 8; j++)
            #pragma unroll
            for (int l = 0; l < 4; l++) acc[i][j][l] = 0.f;

    const int frow = tid >> 1;          // 0..127
    const int fks  = (tid & 1) << 4;    // 0 or 16 shorts

    #pragma unroll 1
    for (int seg = 0; seg < 2; seg++) {
        const int kb = seg ? s0b : s0a, ke = seg ? s1b : s1a;
        #pragma unroll 1
        for (int k0 = kb; k0 < ke; k0 += 32) {
            // ---- A fill (always 16B aligned) ----
            {
                uint4 vh0, vh1, vl0, vl1;
                if (m0 + frow < M) {
                    size_t off = (size_t)(m0 + frow) * lda + k0 + fks;
                    vh0 = *(const uint4*)(Ah + off); vh1 = *(const uint4*)(Ah + off + 8);
                    vl0 = *(const uint4*)(Al + off); vl1 = *(const uint4*)(Al + off + 8);
                } else {
                    vh0 = vh1 = vl0 = vl1 = make_uint4(0, 0, 0, 0);
                }
                *(uint4*)&sAh[frow * 40 + fks]     = vh0;
                *(uint4*)&sAh[frow * 40 + fks + 8] = vh1;
                *(uint4*)&sAl[frow * 40 + fks]     = vl0;
                *(uint4*)&sAl[frow * 40 + fks + 8] = vl1;
            }
            // ---- B fill ----
            {
                uint4 vh0, vh1, vl0, vl1;
                if (n0 + frow < N) {
                    size_t off = (size_t)(n0 + frow) * ldb + k0 + fks;
                    if (balign) {
                        vh0 = *(const uint4*)(Bh + off); vh1 = *(const uint4*)(Bh + off + 8);
                        vl0 = *(const uint4*)(Bl + off); vl1 = *(const uint4*)(Bl + off + 8);
                    } else {            // 4B-aligned only
                        unsigned wh[8], wl[8];
                        #pragma unroll
                        for (int j = 0; j < 8; j++) {
                            wh[j] = *(const unsigned*)(Bh + off + 2 * j);
                            wl[j] = *(const unsigned*)(Bl + off + 2 * j);
                        }
                        vh0 = make_uint4(wh[0], wh[1], wh[2], wh[3]);
                        vh1 = make_uint4(wh[4], wh[5], wh[6], wh[7]);
                        vl0 = make_uint4(wl[0], wl[1], wl[2], wl[3]);
                        vl1 = make_uint4(wl[4], wl[5], wl[6], wl[7]);
                    }
                } else {
                    vh0 = vh1 = vl0 = vl1 = make_uint4(0, 0, 0, 0);
                }
                *(uint4*)&sBh[frow * 40 + fks]     = vh0;
                *(uint4*)&sBh[frow * 40 + fks + 8] = vh1;
                *(uint4*)&sBl[frow * 40 + fks]     = vl0;
                *(uint4*)&sBl[frow * 40 + fks + 8] = vl1;
            }
            __syncthreads();

            #pragma unroll
            for (int kk = 0; kk < 32; kk += 16) {
                unsigned ah[2][4], al[2][4];
                #pragma unroll
                for (int mt = 0; mt < 2; mt++) {
                    const int r = wm * 32 + mt * 16 + g;
                    ah[mt][0] = *(unsigned*)&sAh[r * 40 + kk + 2 * tq];
                    ah[mt][1] = *(unsigned*)&sAh[(r + 8) * 40 + kk + 2 * tq];
                    ah[mt][2] = *(unsigned*)&sAh[r * 40 + kk + 8 + 2 * tq];
                    ah[mt][3] = *(unsigned*)&sAh[(r + 8) * 40 + kk + 8 + 2 * tq];
                    al[mt][0] = *(unsigned*)&sAl[r * 40 + kk + 2 * tq];
                    al[mt][1] = *(unsigned*)&sAl[(r + 8) * 40 + kk + 2 * tq];
                    al[mt][2] = *(unsigned*)&sAl[r * 40 + kk + 8 + 2 * tq];
                    al[mt][3] = *(unsigned*)&sAl[(r + 8) * 40 + kk + 8 + 2 * tq];
                }
                #pragma unroll
                for (int nt = 0; nt < 8; nt++) {
                    const int c = wn * 64 + nt * 8 + g;
                    unsigned bh0 = *(unsigned*)&sBh[c * 40 + kk + 2 * tq];
                    unsigned bh1 = *(unsigned*)&sBh[c * 40 + kk + 8 + 2 * tq];
                    unsigned bl0 = *(unsigned*)&sBl[c * 40 + kk + 2 * tq];
                    unsigned bl1 = *(unsigned*)&sBl[c * 40 + kk + 8 + 2 * tq];
                    #pragma unroll
                    for (int mt = 0; mt < 2; mt++) {
                        MMA_BF16(acc[mt][nt], ah[mt], bh0, bh1);
                        MMA_BF16(acc[mt][nt], ah[mt], bl0, bl1);
                        MMA_BF16(acc[mt][nt], al[mt], bh0, bh1);
                    }
                }
            }
            __syncthreads();
        }
    }

    // ---- epilogue ----
    if (Cf) Cf += (long)blockIdx.z * Csz;
    else { Ch += (long)blockIdx.z * Csz; Cl += (long)blockIdx.z * Csz; }
    #pragma unroll
    for (int mt = 0; mt < 2; mt++) {
        const int r = m0 + wm * 32 + mt * 16 + g;
        #pragma unroll
        for (int nt = 0; nt < 8; nt++) {
            const int c = n0 + wn * 64 + nt * 8 + 2 * tq;
            #pragma unroll
            for (int half = 0; half < 2; half++) {
                const int rr = r + half * 8;
                if (rr >= M) continue;
                #pragma unroll
                for (int jj = 0; jj < 2; jj++) {
                    const int cc = c + jj;
                    if (cc >= N) continue;
                    float v = acc[mt][nt][half * 2 + jj];
                    if (ep == 0)      v += bias[cc];
                    else if (ep == 1) v = (v + bias[cc]) * gate[cond_of_row(rr) * DM + cc];
                    else if (ep == 2) v *= scale;
                    if (Cf) Cf[(size_t)rr * ldc + cc] = v;
                    else {
                        ush h = f2bf(v);
                        Ch[(size_t)rr * ldc + cc] = h;
                        Cl[(size_t)rr * ldc + cc] = f2bf(v - bf2f(h));
                    }
                }
            }
        }
    }
}

// ---------------- weight convert+transpose: W[K][N] fp32 -> D[N][K] bf16 pair ----------------
__global__ __launch_bounds__(256) void wcvt(
    const float* __restrict__ W, int K, int N,
    ush* __restrict__ Dh, ush* __restrict__ Dl, int ldd)
{
    __shared__ float t[32][33];
    const int n0 = blockIdx.x * 32, k0 = blockIdx.y * 32;
    const int tx = threadIdx.x & 31, ty = threadIdx.x >> 5;
    for (int i = ty; i < 32; i += 8) {
        int k = k0 + i, n = n0 + tx;
        t[i][tx] = (k < K && n < N) ? W[(size_t)k * N + n] : 0.f;
    }
    __syncthreads();
    for (int i = ty; i < 32; i += 8) {
        int n = n0 + i, k = k0 + tx;
        if (n < N && k < K) {
            float x = t[tx][i];
            ush h = f2bf(x);
            Dh[(size_t)n * ldd + k] = h;
            Dl[(size_t)n * ldd + k] = f2bf(x - bf2f(h));
        }
    }
}

// ---------------- V transpose: QKV bf16 pair -> VT[h*64+d][key] ----------------
__global__ __launch_bounds__(256) void vt_kernel()
{
    __shared__ ush th[32][33], tl[32][33];
    const int k0 = blockIdx.x * 32, d0 = blockIdx.y * 32;
    const int tx = threadIdx.x & 31, ty = threadIdx.x >> 5;
    for (int i = ty; i < 32; i += 8) {
        int key = k0 + i;
        ush vh = 0, vl = 0;
        if (key < LTOT) {
            size_t o = (size_t)key * 1536 + 1024 + d0 + tx;
            vh = g_QKVh[o]; vl = g_QKVl[o];
        }
        th[i][tx] = vh; tl[i][tx] = vl;
    }
    __syncthreads();
    for (int i = ty; i < 32; i += 8) {
        int d = d0 + i;
        g_VTh[(size_t)d * KP_C + k0 + tx] = th[tx][i];
        g_VTl[(size_t)d * KP_C + k0 + tx] = tl[tx][i];
    }
}

// ---------------- all cond GEMMs, all layers, one launch ----------------
__global__ __launch_bounds__(256) void condall(
    const float* __restrict__ Wm1, const float* __restrict__ bm1,
    const float* __restrict__ Wm2, const float* __restrict__ bm2,
    const float* __restrict__ Wg1, const float* __restrict__ bg1,
    const float* __restrict__ Wg2, const float* __restrict__ bg2)
{
    __shared__ float sA[7 * 512];
    __shared__ float red[256 * 7];
    const int layer = blockIdx.y;
    const int col0 = blockIdx.x * 64;
    const float* W; const float* bias; const float* Asrc; float* dst;
    int ldw, n, nout;
    if (col0 < 1024)      { W = Wm1 + (size_t)layer * 512 * 1024; bias = bm1 + layer * 1024; Asrc = g_SIL;  dst = g_MOD1 + layer * 7168; ldw = 1024; n = col0;        nout = 1024; }
    else if (col0 < 2048) { W = Wm2 + (size_t)layer * 512 * 1024; bias = bm2 + layer * 1024; Asrc = g_SIL;  dst = g_MOD2 + layer * 7168; ldw = 1024; n = col0 - 1024; nout = 1024; }
    else if (col0 < 2560) { W = Wg1 + (size_t)layer * 512 * 512;  bias = bg1 + layer * 512;  Asrc = g_COND; dst = g_G1   + layer * 3584; ldw = 512;  n = col0 - 2048; nout = 512; }
    else                  { W = Wg2 + (size_t)layer * 512 * 512;  bias = bg2 + layer * 512;  Asrc = g_COND; dst = g_G2   + layer * 3584; ldw = 512;  n = col0 - 2560; nout = 512; }

    for (int i = threadIdx.x; i < 7 * 512; i += 256) sA[i] = Asrc[i];
    __syncthreads();
    const int c = threadIdx.x & 63, p = threadIdx.x >> 6;
    float acc[7] = {};
    for (int k = p * 128; k < p * 128 + 128; k++) {
        float w = W[(size_t)k * ldw + n + c];
        #pragma unroll
        for (int m = 0; m < 7; m++) acc[m] += sA[m * 512 + k] * w;
    }
    #pragma unroll
    for (int m = 0; m < 7; m++) red[threadIdx.x * 7 + m] = acc[m];
    __syncthreads();
    if (threadIdx.x < 64) {
        const int cc = threadIdx.x;
        float b = bias[n + cc];
        #pragma unroll
        for (int m = 0; m < 7; m++) {
            float v = red[(0 * 64 + cc) * 7 + m] + red[(1 * 64 + cc) * 7 + m]
                    + red[(2 * 64 + cc) * 7 + m] + red[(3 * 64 + cc) * 7 + m];
            dst[m * nout + n + cc] = v + b;
        }
    }
}

// ---------------- merged QKV bias ----------------
__global__ __launch_bounds__(256) void bmerge(
    const float* __restrict__ bq, const float* __restrict__ bk, const float* __restrict__ bv)
{
    int idx = blockIdx.x * 256 + threadIdx.x;
    if (idx >= NBLK * 1536) return;
    int layer = idx / 1536, nn = idx % 1536;
    int sel = nn >> 9, col = nn & 511;
    const float* b = (sel == 0) ? bq : (sel == 1) ? bk : bv;
    g_bQKV[idx] = b[layer * 512 + col];
}

// ---------------- masked softmax: S fp32 -> P bf16 pair (union-zeroed) ----------------
__global__ __launch_bounds__(256) void softmax_cross()
{
    const int r = blockIdx.x, h = blockIdx.y;
    const size_t base = (size_t)h * L_ZR * KP_C + (size_t)r * KP_C;
    const float* row = g_S + base;
    ush* ph = g_Ph + base; ush* pl = g_Pl + base;
    const int fq = r / SEQ;
    const int a0 = fq * SEQ, a1 = a0 + SEQ;
    const int j0 = (fq >= 4) ? (fq - 4) : 0;
    const int b0 = L_ZR + j0 * SEQ, b1 = L_ZR + fq * SEQ;
    // tile union (must match tcgemm mm==2)
    const int m0 = (r >> 7) << 7;
    const int f0 = m0 / SEQ, f1 = min(m0 + 127, L_ZR - 1) / SEQ;
    int ra0 = (f0 * SEQ) & ~31, ra1 = ((f1 + 1) * SEQ + 31) & ~31;
    int tb0 = L_ZR + ((f0 > 4) ? (f0 - 4) : 0) * SEQ, tb1 = L_ZR + f1 * SEQ;
    int rb0 = tb0 & ~31, rb1 = (tb1 + 31) & ~31;
    if (tb1 <= tb0) { rb0 = 0; rb1 = 0; }
    if (rb1 > rb0 && rb0 < ra1) rb0 = ra1;

    float m = -1e30f;
    for (int j = a0 + threadIdx.x; j < a1; j += 256) m = fmaxf(m, row[j]);
    for (int j = b0 + threadIdx.x; j < b1; j += 256) m = fmaxf(m, row[j]);
    m = blockReduceMax(m);
    float s = 0.f;
    for (int j = a0 + threadIdx.x; j < a1; j += 256) s += expf(row[j] - m);
    for (int j = b0 + threadIdx.x; j < b1; j += 256) s += expf(row[j] - m);
    s = blockReduceSum(s);
    const float inv = 1.f / s;
    // zero the tile union, then write exact values
    for (int j = ra0 + threadIdx.x; j < ra1; j += 256) { ph[j] = 0; pl[j] = 0; }
    for (int j = rb0 + threadIdx.x; j < rb1; j += 256) { ph[j] = 0; pl[j] = 0; }
    __syncthreads();
    for (int j = a0 + threadIdx.x; j < a1; j += 256) {
        float e = expf(row[j] - m) * inv;
        ush hh = f2bf(e); ph[j] = hh; pl[j] = f2bf(e - bf2f(hh));
    }
    for (int j = b0 + threadIdx.x; j < b1; j += 256) {
        float e = expf(row[j] - m) * inv;
        ush hh = f2bf(e); ph[j] = hh; pl[j] = f2bf(e - bf2f(hh));
    }
}

__global__ __launch_bounds__(256) void softmax_self()
{
    const int r = blockIdx.x, h = blockIdx.y;
    const float* row = g_S + (size_t)h * L_XA * KP_S + (size_t)r * KP_S;
    ush* ph = g_PSh + (size_t)h * L_XA * KP_S + (size_t)r * KP_S;
    ush* pl = g_PSl + (size_t)h * L_XA * KP_S + (size_t)r * KP_S;
    const int fq = r / SEQ;
    const int a1 = (fq + 1) * SEQ;
    const int m0 = (r >> 7) << 7;
    const int f1 = min(m0 + 127, L_XA - 1) / SEQ;
    const int r1 = ((f1 + 1) * SEQ + 31) & ~31;

    float m = -1e30f;
    for (int j = threadIdx.x; j < a1; j += 256) m = fmaxf(m, row[j]);
    m = blockReduceMax(m);
    float s = 0.f;
    for (int j = threadIdx.x; j < a1; j += 256) s += expf(row[j] - m);
    s = blockReduceSum(s);
    const float inv = 1.f / s;
    for (int j = threadIdx.x; j < r1; j += 256) { ph[j] = 0; pl[j] = 0; }
    __syncthreads();
    for (int j = threadIdx.x; j < a1; j += 256) {
        float e = expf(row[j] - m) * inv;
        ush hh = f2bf(e); ph[j] = hh; pl[j] = f2bf(e - bf2f(hh));
    }
}

// ---------------- embedding ----------------
__global__ __launch_bounds__(256) void embed_kernel(
    const float* __restrict__ z, const float* __restrict__ frames,
    const int* __restrict__ actions,
    const float* __restrict__ Wp, const float* __restrict__ bp,
    const float* __restrict__ regs, const float* __restrict__ pe,
    const float* __restrict__ aemb)
{
    const int r = blockIdx.x;
    const bool isZ = (r < L_ZR);
    const int f = isZ ? (r / SEQ) : ((r - L_ZR) / SEQ);
    const int t = isZ ? (r % SEQ) : ((r - L_ZR) % SEQ);
    __shared__ float pv[12];
    if (t < 256 && threadIdx.x < 12) {
        int c = threadIdx.x >> 2, py = (threadIdx.x >> 1) & 1, px = threadIdx.x & 1;
        int ph = t >> 4, pw = t & 15;
        const float* src = isZ ? (z + f * 3072) : (frames + f * 3072);
        pv[threadIdx.x] = src[c * 1024 + (ph * 2 + py) * 32 + (pw * 2 + px)];
    }
    __syncthreads();
    for (int d = threadIdx.x; d < DM; d += 256) {
        float val;
        if (t == 256) {
            val = isZ ? regs[d] : aemb[actions[f] * DM + d];
        } else {
            float s = bp[d] + pe[t * DM + d];
            #pragma unroll
            for (int k = 0; k < 12; k++) s += pv[k] * Wp[k * DM + d];
            val = s;
        }
        g_ACT[(size_t)r * DM + d] = val;
    }
}

// ---------------- cond vectors ----------------
__global__ __launch_bounds__(256) void cond_kernel(
    const float* __restrict__ temb, const int* __restrict__ ts)
{
    const int c = blockIdx.x;
    const int row = (c < 6) ? ts[c] : 0;
    for (int d = threadIdx.x; d < DM; d += 256) {
        float v = temb[(size_t)row * DM + d];
        g_COND[c * DM + d] = v;
        g_SIL[c * DM + d] = v / (1.f + expf(-v));
    }
}

// ---------------- LN + AdaLN: writes NRM fp32 + bf16 pair ----------------
__global__ __launch_bounds__(256) void lnmod_kernel(const float* __restrict__ MOD)
{
    const int r = blockIdx.x;
    const int cidx = cond_of_row(r);
    const size_t base = (size_t)r * DM;
    const int d0 = threadIdx.x, d1 = threadIdx.x + 256;
    float v0 = g_ACT[base + d0], v1 = g_ACT[base + d1];
    float mu = blockReduceSum(v0 + v1) * (1.f / 512.f);
    float c0 = v0 - mu, c1 = v1 - mu;
    float var = blockReduceSum(c0 * c0 + c1 * c1) * (1.f / 512.f);
    float inv = rsqrtf(var + 1e-5f);
    const float* sc = MOD + cidx * 1024;
    float y0 = c0 * inv * (1.f + sc[d0]) + sc[512 + d0];
    float y1 = c1 * inv * (1.f + sc[d1]) + sc[512 + d1];
    g_NRM[base + d0] = y0; g_NRM[base + d1] = y1;
    ush h0 = f2bf(y0), h1 = f2bf(y1);
    g_NRMh[base + d0] = h0; g_NRMl[base + d0] = f2bf(y0 - bf2f(h0));
    g_NRMh[base + d1] = h1; g_NRMl[base + d1] = f2bf(y1 - bf2f(h1));
}

// ---------------- gate1*NRM + attnO, LN + mod2 -> B1 bf16 pair ----------------
__global__ __launch_bounds__(256) void gatereslnmod_kernel(
    const float* __restrict__ G, const float* __restrict__ MOD)
{
    const int r = blockIdx.x;
    const int cidx = cond_of_row(r);
    const size_t base = (size_t)r * DM;
    const int d0 = threadIdx.x, d1 = threadIdx.x + 256;
    float u0 = g_NRM[base + d0] * G[cidx * 512 + d0] + g_O[base + d0];
    float u1 = g_NRM[base + d1] * G[cidx * 512 + d1] + g_O[base + d1];
    float mu = blockReduceSum(u0 + u1) * (1.f / 512.f);
    float c0 = u0 - mu, c1 = u1 - mu;
    float var = blockReduceSum(c0 * c0 + c1 * c1) * (1.f / 512.f);
    float inv = rsqrtf(var + 1e-5f);
    const float* sc = MOD + cidx * 1024;
    float y0 = c0 * inv * (1.f + sc[d0]) + sc[512 + d0];
    float y1 = c1 * inv * (1.f + sc[d1]) + sc[512 + d1];
    ush h0 = f2bf(y0), h1 = f2bf(y1);
    g_B1h[base + d0] = h0; g_B1l[base + d0] = f2bf(y0 - bf2f(h0));
    g_B1h[base + d1] = h1; g_B1l[base + d1] = f2bf(y1 - bf2f(h1));
}

// ---------------- GEGLU: FF1 fp32 -> H bf16 pair ----------------
__global__ __launch_bounds__(256) void geglu_kernel()
{
    int idx = blockIdx.x * 256 + threadIdx.x;
    if (idx >= LTOT * HID) return;
    int r = idx / HID, c = idx % HID;
    float a = g_FF1[(size_t)r * (2 * HID) + c];
    float g = g_FF1[(size_t)r * (2 * HID) + HID + c];
    float v = a * 0.5f * g * (1.f + erff(g * 0.70710678118654752f));
    ush h = f2bf(v);
    g_Hh[idx] = h; g_Hl[idx] = f2bf(v - bf2f(h));
}

// ---------------- unpatch ----------------
__global__ __launch_bounds__(256) void unpatch_kernel(
    const float* __restrict__ Wu, const float* __restrict__ bu, float* __restrict__ out)
{
    int idx = blockIdx.x * 256 + threadIdx.x;
    if (idx >= FZR * 256 * 12) return;
    int j = idx % 12, tl = idx / 12;
    int f = tl >> 8, t = tl & 255;
    const float* a = g_ACT + (size_t)(f * SEQ + t) * DM;
    float s = bu[j];
    #pragma unroll 4
    for (int d = 0; d < DM; d++) s += a[d] * Wu[d * 12 + j];
    int c = j >> 2, py = (j >> 1) & 1, px = j & 1;
    int ph = t >> 4, pw = t & 15;
    out[f * 3072 + c * 1024 + (ph * 2 + py) * 32 + (pw * 2 + px)] = s;
}

// ---------------- host orchestration ----------------
extern "C" void kernel_launch(void* const* d_in, const int* in_sizes, int n_in,
                              void* d_out, int out_size)
{
    const float* z      = (const float*)d_in[0];
    const float* frames = (const float*)d_in[1];
    const int*   actions= (const int*)  d_in[2];
    const int*   ts     = (const int*)  d_in[3];
    const float* Wp     = (const float*)d_in[4];
    const float* bp     = (const float*)d_in[5];
    const float* Wu     = (const float*)d_in[6];
    const float* bu     = (const float*)d_in[7];
    const float* regs   = (const float*)d_in[8];
    const float* pe     = (const float*)d_in[9];
    const float* aemb   = (const float*)d_in[10];
    const float* temb   = (const float*)d_in[11];
    const float* Wm1    = (const float*)d_in[12];
    const float* bm1    = (const float*)d_in[13];
    const float* Wm2    = (const float*)d_in[14];
    const float* bm2    = (const float*)d_in[15];
    const float* Wq     = (const float*)d_in[16];
    const float* bq     = (const float*)d_in[17];
    const float* Wk     = (const float*)d_in[18];
    const float* bk     = (const float*)d_in[19];
    const float* Wv     = (const float*)d_in[20];
    const float* bv     = (const float*)d_in[21];
    const float* Wo     = (const float*)d_in[22];
    const float* bo     = (const float*)d_in[23];
    const float* Wg1    = (const float*)d_in[24];
    const float* bg1    = (const float*)d_in[25];
    const float* Wg2    = (const float*)d_in[26];
    const float* bg2    = (const float*)d_in[27];
    const float* Wge    = (const float*)d_in[28];
    const float* bge    = (const float*)d_in[29];
    const float* Wff    = (const float*)d_in[30];
    const float* bff    = (const float*)d_in[31];

    float *S, *MOD1, *MOD2, *G1, *G2, *bQKV, *FF1, *ACT, *O;
    ush *NRMh,*NRMl,*QKVh,*QKVl,*VTh,*VTl,*Ph,*Pl,*PSh,*PSl,*ATTh,*ATTl,*B1h,*B1l,*Hh,*Hl;
    ush *Wqkvh,*Wqkvl,*Woh,*Wol,*Wgeh,*Wgel,*Wffh,*Wffl;
    cudaGetSymbolAddress((void**)&S,     g_S);
    cudaGetSymbolAddress((void**)&MOD1,  g_MOD1);
    cudaGetSymbolAddress((void**)&MOD2,  g_MOD2);
    cudaGetSymbolAddress((void**)&G1,    g_G1);
    cudaGetSymbolAddress((void**)&G2,    g_G2);
    cudaGetSymbolAddress((void**)&bQKV,  g_bQKV);
    cudaGetSymbolAddress((void**)&FF1,   g_FF1);
    cudaGetSymbolAddress((void**)&ACT,   g_ACT);
    cudaGetSymbolAddress((void**)&O,     g_O);
    cudaGetSymbolAddress((void**)&NRMh,  g_NRMh);  cudaGetSymbolAddress((void**)&NRMl, g_NRMl);
    cudaGetSymbolAddress((void**)&QKVh,  g_QKVh);  cudaGetSymbolAddress((void**)&QKVl, g_QKVl);
    cudaGetSymbolAddress((void**)&VTh,   g_VTh);   cudaGetSymbolAddress((void**)&VTl,  g_VTl);
    cudaGetSymbolAddress((void**)&Ph,    g_Ph);    cudaGetSymbolAddress((void**)&Pl,   g_Pl);
    cudaGetSymbolAddress((void**)&PSh,   g_PSh);   cudaGetSymbolAddress((void**)&PSl,  g_PSl);
    cudaGetSymbolAddress((void**)&ATTh,  g_ATTh);  cudaGetSymbolAddress((void**)&ATTl, g_ATTl);
    cudaGetSymbolAddress((void**)&B1h,   g_B1h);   cudaGetSymbolAddress((void**)&B1l,  g_B1l);
    cudaGetSymbolAddress((void**)&Hh,    g_Hh);    cudaGetSymbolAddress((void**)&Hl,   g_Hl);
    cudaGetSymbolAddress((void**)&Wqkvh, g_Wqkvh); cudaGetSymbolAddress((void**)&Wqkvl,g_Wqkvl);
    cudaGetSymbolAddress((void**)&Woh,   g_Woh);   cudaGetSymbolAddress((void**)&Wol,  g_Wol);
    cudaGetSymbolAddress((void**)&Wgeh,  g_Wgeh);  cudaGetSymbolAddress((void**)&Wgel, g_Wgel);
    cudaGetSymbolAddress((void**)&Wffh,  g_Wffh);  cudaGetSymbolAddress((void**)&Wffl, g_Wffl);

    embed_kernel<<<LTOT, 256>>>(z, frames, actions, Wp, bp, regs, pe, aemb);
    cond_kernel<<<7, 256>>>(temb, ts);
    condall<<<dim3(48, 6), 256>>>(Wm1, bm1, Wm2, bm2, Wg1, bg1, Wg2, bg2);
    bmerge<<<CDIV(NBLK * 1536, 256), 256>>>(bq, bk, bv);

    // weight pre-convert (transposed to [N][K] bf16 pairs)
    for (int i = 0; i < NBLK; i++) {
        size_t wq = (size_t)i * 512 * 512, wg = (size_t)i * 4096 * 512, wf = (size_t)i * 512 * 2048;
        size_t dq = (size_t)i * 1536 * 512;
        wcvt<<<dim3(16, 16), 256>>>(Wq + wq, 512, 512, Wqkvh + dq,             Wqkvl + dq,             512);
        wcvt<<<dim3(16, 16), 256>>>(Wk + wq, 512, 512, Wqkvh + dq + 512 * 512, Wqkvl + dq + 512 * 512, 512);
        wcvt<<<dim3(16, 16), 256>>>(Wv + wq, 512, 512, Wqkvh + dq + 1024 * 512,Wqkvl + dq + 1024 * 512,512);
        wcvt<<<dim3(16, 16), 256>>>(Wo + wq, 512, 512, Woh + wq, Wol + wq, 512);
        wcvt<<<dim3(128, 16), 256>>>(Wge + wg, 512, 4096, Wgeh + wg, Wgel + wg, 512);
        wcvt<<<dim3(16, 64), 256>>>(Wff + wf, 2048, 512, Wffh + wf, Wffl + wf, 2048);
    }

    const long SC = (long)L_ZR * KP_C;
    const long SSm = (long)L_XA * KP_S;

    for (int i = 0; i < NBLK; i++) {
        const float* boi  = bo  + (size_t)i * DM;
        const float* bgei = bge + (size_t)i * 2 * HID;
        const float* bffi = bff + (size_t)i * DM;

        lnmod_kernel<<<LTOT, 256>>>(MOD1 + i * 7168);

        // QKV projection -> bf16 pair [LTOT][1536]
        tcgemm_bf<<<dim3(12, 23, 1), 256>>>(
            NRMh, NRMl, 512, 0, Wqkvh + (size_t)i * 1536 * 512, Wqkvl + (size_t)i * 1536 * 512, 512, 0, 1,
            bQKV + i * 1536, nullptr, QKVh, QKVl, 1536, 0, LTOT, 1536, 512, 0, nullptr, 0.f, 0);

        vt_kernel<<<dim3(CDIV(KP_C, 32), 16), 256>>>();

        // ---- cross attention ----
        tcgemm_bf<<<dim3(CDIV(LTOT, 128), CDIV(L_ZR, 128), NHEAD), 256>>>(
            QKVh, QKVl, 1536, 64, QKVh + 512, QKVl + 512, 1536, 64, 1,
            nullptr, S, nullptr, nullptr, KP_C, SC, L_ZR, LTOT, 64, 1, nullptr, 0.125f, 2);
        softmax_cross<<<dim3(L_ZR, NHEAD), 256>>>();
        tcgemm_bf<<<dim3(1, CDIV(L_ZR, 128), NHEAD), 256>>>(
            Ph, Pl, KP_C, SC, VTh, VTl, KP_C, 64 * (long)KP_C, 1,
            nullptr, nullptr, ATTh, ATTl, 512, 64, L_ZR, 64, LTOT, 2, nullptr, 0.f, 3);

        // ---- self attention ----
        tcgemm_bf<<<dim3(CDIV(L_XA, 128), CDIV(L_XA, 128), NHEAD), 256>>>(
            QKVh + (size_t)L_ZR * 1536, QKVl + (size_t)L_ZR * 1536, 1536, 64,
            QKVh + (size_t)L_ZR * 1536 + 512, QKVl + (size_t)L_ZR * 1536 + 512, 1536, 64, 1,
            nullptr, S, nullptr, nullptr, KP_S, SSm, L_XA, L_XA, 64, 3, nullptr, 0.125f, 2);
        softmax_self<<<dim3(L_XA, NHEAD), 256>>>();
        tcgemm_bf<<<dim3(1, CDIV(L_XA, 128), NHEAD), 256>>>(
            PSh, PSl, KP_S, SSm, VTh + L_ZR, VTl + L_ZR, KP_C, 64 * (long)KP_C, 0,
            nullptr, nullptr, ATTh + (size_t)L_ZR * 512, ATTl + (size_t)L_ZR * 512, 512, 64,
            L_XA, 64, L_XA, 4, nullptr, 0.f, 3);

        // output projection -> O fp32
        tcgemm_bf<<<dim3(4, 23, 1), 256>>>(
            ATTh, ATTl, 512, 0, Woh + (size_t)i * 512 * 512, Wol + (size_t)i * 512 * 512, 512, 0, 1,
            boi, O, nullptr, nullptr, 512, 0, LTOT, 512, 512, 0, nullptr, 0.f, 0);

        gatereslnmod_kernel<<<LTOT, 256>>>(G1 + i * 3584, MOD2 + i * 7168);

        // FFN
        tcgemm_bf<<<dim3(32, 23, 1), 256>>>(
            B1h, B1l, 512, 0, Wgeh + (size_t)i * 4096 * 512, Wgel + (size_t)i * 4096 * 512, 512, 0, 1,
            bgei, FF1, nullptr, nullptr, 4096, 0, LTOT, 4096, 512, 0, nullptr, 0.f, 0);
        geglu_kernel<<<CDIV(LTOT * HID, 256), 256>>>();
        tcgemm_bf<<<dim3(4, 23, 1), 256>>>(
            Hh, Hl, 2048, 0, Wffh + (size_t)i * 512 * 2048, Wffl + (size_t)i * 512 * 2048, 2048, 0, 1,
            bffi, ACT, nullptr, nullptr, 512, 0, LTOT, 512, 2048, 0, G2 + i * 3584, 0.f, 1);
    }

    unpatch_kernel<<<CDIV(FZR * 256 * 12, 256), 256>>>(Wu, bu, (float*)d_out);
}